// round 8
// baseline (speedup 1.0000x reference)
#include <cuda_runtime.h>
#include <cuda_fp16.h>

// Problem constants (DgaRawSequence: B=256, T=8192, I=6, U=64, M=16)
#define NB 256
#define NT 8192
#define NI 6
#define NU 64
#define NM 16
#define UNFOLDS 6
#define EPSV 1e-8f

__device__ __forceinline__ float tanhf_(float v) {
    float y; asm("tanh.approx.f32 %0, %1;" : "=f"(y) : "f"(v)); return y;
}
__device__ __forceinline__ unsigned tanh2_(unsigned v) {
    unsigned y; asm("tanh.approx.f16x2 %0, %1;" : "=r"(y) : "r"(v)); return y;
}
__device__ __forceinline__ float rcpf_(float v) {
    float y; asm("rcp.approx.f32 %0, %1;" : "=f"(y) : "f"(v)); return y;
}

// sigmoid(z) = 0.5 + 0.5*tanh(z/2), 0.5's folded into weights.
// Block = 128 threads = 64 u x 2 c (32 presynaptic j each); one block per
// batch (grid=256, 2 blocks/SM). HYBRID precision: v kept f32 in shared,
// z computed in f32 for ALL synapses; synapses k=0..15 use tanh.approx.f32,
// k=16..31 are evaluated pairwise with cvt.rn.f16x2.f32 + tanh.approx.f16x2
// (only f16 error source = tanh output quantization, on half the synapses).
// MUFU burst: 24 inst/thread/unfold (vs 32 all-f32, vs 16 all-f16 which is
// FMA-bound at the same period anyway).
__global__ void __launch_bounds__(128, 2) ltc_seq_kernel(
    const float* __restrict__ x,
    const float* __restrict__ gleak, const float* __restrict__ vleak,
    const float* __restrict__ cm,
    const float* __restrict__ sigma, const float* __restrict__ mu,
    const float* __restrict__ w,     const float* __restrict__ erev,
    const float* __restrict__ ssigma, const float* __restrict__ smu,
    const float* __restrict__ swv,    const float* __restrict__ serev,
    const float* __restrict__ in_w,  const float* __restrict__ in_b,
    const float* __restrict__ out_w, const float* __restrict__ out_b,
    float* __restrict__ out)
{
    const int tid = threadIdx.x;
    const int u   = tid >> 1;
    const int c   = tid & 1;
    const int b   = blockIdx.x;

    __shared__ __align__(16) float vbuf[2][NU];

    // ---- per-(j,u) recurrent params in registers, j = 32*c + k ----
    float p_na[32], p_tb[32], p_wh[32], p_weh[32];
    float denb = 0.f, numb = 0.f;
#pragma unroll
    for (int k = 0; k < 32; k++) {
        int j = c * 32 + k;
        float sg = sigma[j * NU + u];
        float m  = mu[j * NU + u];
        float ww = w[j * NU + u];
        float er = erev[j * NU + u];
        p_na[k]  = 0.5f * sg;            // multiplies v (z/2)
        p_tb[k]  = -0.5f * m * sg;       // constant term
        p_wh[k]  = 0.5f * ww;
        p_weh[k] = 0.5f * ww * er;
        denb += p_wh[k];
        numb += p_weh[k];
    }

    // ---- sensory params: lane c handles i = 3c, 3c+1, 3c+2 (f32 path) ----
    float s_na[3], s_tb[3], s_wh[3], s_weh[3], s_iw[3], s_ib[3];
    float s_base_d = 0.f, s_base_n = 0.f;
#pragma unroll
    for (int ii = 0; ii < 3; ii++) {
        int i = c * 3 + ii;
        float sg = ssigma[i * NU + u], m = smu[i * NU + u];
        float ww = swv[i * NU + u],    er = serev[i * NU + u];
        s_na[ii]  = 0.5f * sg;
        s_tb[ii]  = -0.5f * m * sg;
        s_wh[ii]  = 0.5f * ww;
        s_weh[ii] = 0.5f * ww * er;
        s_base_d += s_wh[ii];
        s_base_n += s_weh[ii];
        s_iw[ii] = in_w[i]; s_ib[ii] = in_b[i];
    }

    // ---- per-u constants ----
    const float cmt  = 6.0f * cm[u];
    const float gl   = gleak[u];
    const float glvl = gl * vleak[u];
    float ow = 0.f, ob = 0.f;
    if (u < NM) { ow = out_w[u]; ob = out_b[u]; }

    // ---- init state v = 0 ----
    if (tid < NU) vbuf[0][tid] = 0.f;
    __syncthreads();
    float vu = 0.f;   // register copy of v(u), redundant in both c-lanes

    const float* xb   = x   + (size_t)b * NT * NI;
    float*       outb = out + (size_t)b * NT * NM;

    float xv[3];
#pragma unroll
    for (int ii = 0; ii < 3; ii++) xv[ii] = xb[c * 3 + ii];

    for (int t = 0; t < NT; t++) {
        // ---- sensory sums (constant across unfolds, f32 tanh) ----
        float ds = s_base_d, ns = s_base_n;
#pragma unroll
        for (int ii = 0; ii < 3; ii++) {
            float xi = fmaf(xv[ii], s_iw[ii], s_ib[ii]);
            float th = tanhf_(fmaf(xi, s_na[ii], s_tb[ii]));
            ds = fmaf(s_wh[ii],  th, ds);
            ns = fmaf(s_weh[ii], th, ns);
        }
        ds += __shfl_xor_sync(0xffffffffu, ds, 1);
        ns += __shfl_xor_sync(0xffffffffu, ns, 1);

        if (t + 1 < NT) {
#pragma unroll
            for (int ii = 0; ii < 3; ii++)
                xv[ii] = xb[(t + 1) * NI + c * 3 + ii];
        }

        const float nn_c = glvl + ns;
        const float dd_c = cmt + gl + ds + EPSV;

#pragma unroll
        for (int s = 0; s < UNFOLDS; s++) {
            const int rb = s & 1;
            const float* vp = vbuf[rb];

            const float4* vp4 = (const float4*)(vp + c * 32);
            float vj[32];
#pragma unroll
            for (int q = 0; q < 8; q++) {
                float4 qq = vp4[q];
                vj[q * 4 + 0] = qq.x; vj[q * 4 + 1] = qq.y;
                vj[q * 4 + 2] = qq.z; vj[q * 4 + 3] = qq.w;
            }

            float den0 = denb, den1 = 0.f, num0 = numb, num1 = 0.f;

            // ---- k = 0..15 : exact f32 tanh path ----
#pragma unroll
            for (int k = 0; k < 16; k++) {
                float th = tanhf_(fmaf(vj[k], p_na[k], p_tb[k]));
                if (k & 1) {
                    den1 = fmaf(p_wh[k],  th, den1);
                    num1 = fmaf(p_weh[k], th, num1);
                } else {
                    den0 = fmaf(p_wh[k],  th, den0);
                    num0 = fmaf(p_weh[k], th, num0);
                }
            }

            // ---- k = 16..31 : f32 z -> f16x2 tanh pairs ----
#pragma unroll
            for (int k = 16; k < 32; k += 2) {
                float z0 = fmaf(vj[k],     p_na[k],     p_tb[k]);
                float z1 = fmaf(vj[k + 1], p_na[k + 1], p_tb[k + 1]);
                __half2 zh = __floats2half2_rn(z0, z1);
                unsigned thu = tanh2_(*(unsigned*)&zh);
                __half2 th2 = *(__half2*)&thu;
                float t0 = __low2float(th2);
                float t1 = __high2float(th2);
                den0 = fmaf(p_wh[k],      t0, den0);
                num0 = fmaf(p_weh[k],     t0, num0);
                den1 = fmaf(p_wh[k + 1],  t1, den1);
                num1 = fmaf(p_weh[k + 1], t1, num1);
            }

            // den reduce FIRST so rcp (16cyc) overlaps num's shfl (26cyc)
            float den = den0 + den1;
            den += __shfl_xor_sync(0xffffffffu, den, 1);
            float num = num0 + num1;
            float r = rcpf_(dd_c + den);
            num += __shfl_xor_sync(0xffffffffu, num, 1);

            float nn = fmaf(cmt, vu, nn_c) + num;
            float vn = nn * r;
            vu = vn;
            if (c == 0) vbuf[rb ^ 1][u] = vn;
            __syncthreads();
        }

        // ---- output: first M motor neurons, affine ----
        if (c == 0 && u < NM) {
            outb[t * NM + u] = fmaf(vu, ow, ob);
        }
    }
}

extern "C" void kernel_launch(void* const* d_in, const int* in_sizes, int n_in,
                              void* d_out, int out_size) {
    (void)in_sizes; (void)n_in; (void)out_size;
    const float* xx     = (const float*)d_in[0];
    const float* gleak  = (const float*)d_in[1];
    const float* vleak  = (const float*)d_in[2];
    const float* cm     = (const float*)d_in[3];
    const float* sigma  = (const float*)d_in[4];
    const float* mu     = (const float*)d_in[5];
    const float* w      = (const float*)d_in[6];
    const float* erev   = (const float*)d_in[7];
    const float* ssig   = (const float*)d_in[8];
    const float* smu    = (const float*)d_in[9];
    const float* sw     = (const float*)d_in[10];
    const float* serev  = (const float*)d_in[11];
    const float* in_w   = (const float*)d_in[12];
    const float* in_b   = (const float*)d_in[13];
    const float* out_w  = (const float*)d_in[14];
    const float* out_b  = (const float*)d_in[15];
    float* out = (float*)d_out;

    ltc_seq_kernel<<<NB, 128>>>(xx, gleak, vleak, cm, sigma, mu, w, erev,
                                ssig, smu, sw, serev, in_w, in_b, out_w, out_b,
                                out);
}